// round 11
// baseline (speedup 1.0000x reference)
#include <cuda_runtime.h>
#include <cuda_fp16.h>
#include <mma.h>
#include <cstdint>

using namespace nvcuda;

// Problem constants
#define BB   2
#define JJ   24
#define DD   32
#define NV   32768           // 32*32*32
#define PX2D (JJ*DD)         // 768
#define NMAT (BB*JJ*DD*NV)   // 50,331,648 elements in An / A

// ---------------------------------------------------------------------------
// Scratch (device globals; no allocation allowed)
// ---------------------------------------------------------------------------
__device__ float g_x2d[BB*7*PX2D];   // [dual(0..4), evalop1(5), g(6)]
__device__ float g_h2a[BB*32*PX2D];
__device__ float g_h2b[BB*32*PX2D];
__device__ float g_y3d[BB*6*NV];     // [primal(0..4), evalop2(5)]
__device__ float g_h3a[BB*32*NV];
__device__ float g_h3b[BB*32*NV];
__device__ float g_f  [BB*NV];       // Fortran-flattened primal channel 1
__device__ __half g_An_h[NMAT];      // fp16 copy of An (built per launch)
__device__ __half g_A_h [NMAT];      // fp16 copy of A
// conv2 weights, exact 3-way tf32 split, layout [iter][ci][n:32][k:32]
// (B col-major: element (k,n) at n*32 + k)
__device__ float g_w2h[10*32*32*32];
__device__ float g_w2m[10*32*32*32];
__device__ float g_w2l[10*32*32*32];

// ---------------------------------------------------------------------------
// tf32 helper: round-to-nearest tf32, returned as float
// ---------------------------------------------------------------------------
__device__ __forceinline__ float f2tf32f(float x) {
    uint32_t u; asm("cvt.rna.tf32.f32 %0, %1;" : "=r"(u) : "f"(x));
    return __uint_as_float(u);
}

// ---------------------------------------------------------------------------
// fp32 -> fp16 conversion (streaming)
// ---------------------------------------------------------------------------
__global__ void cvt_half_kernel(const float* __restrict__ src,
                                __half2* __restrict__ dst, int n4) {
    int i = blockIdx.x * blockDim.x + threadIdx.x;
    if (i >= n4) return;
    float4 v = __ldcs(reinterpret_cast<const float4*>(src) + i);
    dst[2*i]   = __floats2half2_rn(v.x, v.y);
    dst[2*i+1] = __floats2half2_rn(v.z, v.w);
}

// ---------------------------------------------------------------------------
// conv2 weight pre-convert: w[iter][co][ci][27] -> exact 3-way tf32 split in
// [iter][ci][n:32][k:32] (B col-major), zero-padded for k>=27.
// ---------------------------------------------------------------------------
__global__ void precvt_w2_kernel(const float* __restrict__ w,
                                 float* __restrict__ hi, float* __restrict__ mid,
                                 float* __restrict__ lo, int total) {
    int idx = blockIdx.x * 256 + threadIdx.x;
    if (idx >= total) return;
    int k  = idx & 31;
    int n  = (idx >> 5) & 31;
    int ci = (idx >> 10) & 31;
    int it = idx >> 15;
    float v = 0.f;
    if (k < 27)
        v = w[(((size_t)it*32 + n)*32 + ci)*27 + k];
    float h = f2tf32f(v);
    float r = v - h;                 // exact
    float m = f2tf32f(r);
    hi[idx]  = h;
    mid[idx] = m;
    lo[idx]  = r - m;                // exact, tf32-representable
}

// ---------------------------------------------------------------------------
// Init: dual -> x2d[0..4], g -> x2d[6], primal -> y3d[0..4], primal ch1 -> g_f
// ---------------------------------------------------------------------------
__global__ void init_kernel(const float* __restrict__ dual,
                            const float* __restrict__ gg,
                            const float* __restrict__ primal) {
    int i = blockIdx.x * blockDim.x + threadIdx.x;
    if (i < BB*5*NV) {
        int b = i / (5*NV); int r = i % (5*NV); int c = r / NV; int v = r % NV;
        g_y3d[(size_t)(b*6 + c)*NV + v] = primal[i];
    }
    if (i < BB*NV) {
        int b = i / NV, v = i % NV;
        int z = v & 31, y = (v >> 5) & 31, x = v >> 10;
        g_f[i] = primal[(size_t)(b*5 + 1)*NV + (z*32 + y)*32 + x];
    }
    if (i < BB*5*PX2D) {
        int b = i / (5*PX2D); int r = i % (5*PX2D); int c = r / PX2D; int p = r % PX2D;
        g_x2d[(size_t)(b*7 + c)*PX2D + p] = dual[i];
    }
    if (i < BB*PX2D) {
        int b = i / PX2D; int p = i % PX2D;
        g_x2d[(size_t)(b*7 + 6)*PX2D + p] = gg[i];
    }
}

// ---------------------------------------------------------------------------
// evalop1[b,j,d] = sum_v An[b,j,d,v] * f[b,v]   (fp16 matrix, fp32 math)
// ---------------------------------------------------------------------------
__global__ void evalop1_kernel() {
    const int row = blockIdx.x;                 // (b*J + j)*D + d
    const int b   = row / PX2D;
    const uint4*  a = reinterpret_cast<const uint4*>(g_An_h) + (size_t)row * (NV/8);
    const float4* f = reinterpret_cast<const float4*>(g_f) + (size_t)b * (NV/4);
    float acc = 0.f;
    #pragma unroll 2
    for (int i = threadIdx.x; i < NV/8; i += 256) {
        uint4 av = __ldcs(a + i);
        float4 f0 = f[2*i], f1 = f[2*i+1];
        float2 p;
        p = __half22float2(*reinterpret_cast<__half2*>(&av.x));
        acc = fmaf(p.x, f0.x, acc); acc = fmaf(p.y, f0.y, acc);
        p = __half22float2(*reinterpret_cast<__half2*>(&av.y));
        acc = fmaf(p.x, f0.z, acc); acc = fmaf(p.y, f0.w, acc);
        p = __half22float2(*reinterpret_cast<__half2*>(&av.z));
        acc = fmaf(p.x, f1.x, acc); acc = fmaf(p.y, f1.y, acc);
        p = __half22float2(*reinterpret_cast<__half2*>(&av.w));
        acc = fmaf(p.x, f1.z, acc); acc = fmaf(p.y, f1.w, acc);
    }
    #pragma unroll
    for (int off = 16; off; off >>= 1) acc += __shfl_down_sync(0xffffffffu, acc, off);
    __shared__ float red[8];
    if ((threadIdx.x & 31) == 0) red[threadIdx.x >> 5] = acc;
    __syncthreads();
    if (threadIdx.x == 0) {
        float s = 0.f;
        #pragma unroll
        for (int i = 0; i < 8; i++) s += red[i];
        g_x2d[(size_t)(b*7 + 5)*PX2D + (row % PX2D)] = s;
    }
}

// ---------------------------------------------------------------------------
// 2D conv 3x3 SAME over (J=24, D=32), register-blocked, float4 weights.
// ---------------------------------------------------------------------------
template<int CIN, bool PRELU, bool RES>
__global__ void __launch_bounds__(192)
conv2d_kernel(const float* __restrict__ in, int in_ct,
              const float* __restrict__ w,
              const float* __restrict__ bias,
              const float* __restrict__ alpha,
              float* __restrict__ out, int out_ct) {
    __shared__ float4 swt4[CIN*3];
    const int co = blockIdx.x;
    const int b  = blockIdx.y;
    const int tid = threadIdx.x;
    {
        float* swts = reinterpret_cast<float*>(swt4);
        for (int i = tid; i < CIN*9; i += 192)
            swts[(i/3)*4 + (i%3)] = w[co*CIN*9 + i];
    }
    __syncthreads();

    const int dg = tid & 7;        // d-chunk 0..7
    const int j  = tid >> 3;       // 0..23
    const int d0 = dg << 2;

    float acc[4] = {0.f, 0.f, 0.f, 0.f};
    const float* xb = in + (size_t)b * in_ct * PX2D;

    for (int ci = 0; ci < CIN; ci++) {
        const float* xc = xb + ci * PX2D;
        #pragma unroll
        for (int kj = 0; kj < 3; kj++) {
            const int jj = j + kj - 1;
            float r[6];
            if (jj >= 0 && jj < JJ) {
                const float* rp = xc + jj*32 + d0;
                float4 m = *reinterpret_cast<const float4*>(rp);
                r[1] = m.x; r[2] = m.y; r[3] = m.z; r[4] = m.w;
                r[0] = (d0 > 0)  ? rp[-1] : 0.f;
                r[5] = (d0 < 28) ? rp[4]  : 0.f;
            } else {
                #pragma unroll
                for (int t = 0; t < 6; t++) r[t] = 0.f;
            }
            const float4 wv = swt4[ci*3 + kj];
            #pragma unroll
            for (int di = 0; di < 4; di++)
                acc[di] = fmaf(wv.x, r[di], fmaf(wv.y, r[di+1], fmaf(wv.z, r[di+2], acc[di])));
        }
    }

    const float a  = PRELU ? alpha[0] : 0.f;
    const float bv = bias[co];
    float* op = out + (size_t)(b*out_ct + co)*PX2D + j*32 + d0;
    #pragma unroll
    for (int di = 0; di < 4; di++) {
        float rr = acc[di] + bv;
        if (PRELU) rr = rr >= 0.f ? rr : a * rr;
        if (RES) op[di] += rr; else op[di] = rr;
    }
}

// ---------------------------------------------------------------------------
// adjoint: back[b,v] = sum_{j,d} A[b,j,v,d] * dual0[b,j,d]   (fp16 matrix)
// ---------------------------------------------------------------------------
__global__ void adjoint_kernel() {
    __shared__ float sd[PX2D];
    const int b  = blockIdx.x / (NV/8);
    const int v0 = (blockIdx.x % (NV/8)) * 8;
    for (int i = threadIdx.x; i < PX2D; i += 256)
        sd[i] = g_x2d[(size_t)(b*7 + 0)*PX2D + i];
    __syncthreads();
    const int wrp = threadIdx.x >> 5, lane = threadIdx.x & 31;
    const int v = v0 + wrp;
    const __half* Ab = g_A_h + (size_t)b * JJ * NV * DD;
    float acc = 0.f;
    #pragma unroll
    for (int j = 0; j < JJ; j++) {
        float av = __half2float(__ldcs(Ab + ((size_t)j*NV + v)*DD + lane));
        acc = fmaf(av, sd[j*DD + lane], acc);
    }
    #pragma unroll
    for (int off = 16; off; off >>= 1) acc += __shfl_down_sync(0xffffffffu, acc, off);
    if (lane == 0) {
        int z = v & 31, y = (v >> 5) & 31, x = v >> 10;
        g_y3d[(size_t)(b*6 + 5)*NV + (z*32 + y)*32 + x] = acc;
    }
}

// ---------------------------------------------------------------------------
// Scalar 3D conv 3x3x3 SAME over 32^3 (R3/R10 geometry, proven).
// ---------------------------------------------------------------------------
template<int CIN, int COPB, bool PRELU, bool RES, bool WRITE_F>
__global__ void __launch_bounds__(128)
conv3d_kernel(const float* __restrict__ in, int in_ct,
              const float* __restrict__ w,
              const float* __restrict__ bias,
              const float* __restrict__ alpha,
              float* __restrict__ out, int out_ct) {
    __shared__ float swt[COPB*CIN*27];
    const int b   = blockIdx.z;
    const int z   = blockIdx.y;
    const int cg  = blockIdx.x;
    const int tid = threadIdx.x;

    for (int i = tid; i < COPB*CIN*27; i += 128)
        swt[i] = w[(size_t)cg*COPB*CIN*27 + i];
    __syncthreads();

    const int xg = tid & 3;
    const int y  = tid >> 2;
    const int x0 = xg << 3;

    float acc[COPB][8];
    #pragma unroll
    for (int c = 0; c < COPB; c++)
        #pragma unroll
        for (int xi = 0; xi < 8; xi++) acc[c][xi] = 0.f;

    for (int ci = 0; ci < CIN; ci++) {
        const float* pc = in + ((size_t)(b*in_ct + ci) << 15);
        #pragma unroll
        for (int kz = 0; kz < 3; kz++) {
            const int zz = z + kz - 1;
            if (zz < 0 || zz >= 32) continue;      // uniform per block
            #pragma unroll
            for (int ky = 0; ky < 3; ky++) {
                const int yy = y + ky - 1;
                float r[10];
                if (yy >= 0 && yy < 32) {
                    const float* rp = pc + ((zz << 5) + yy)*32 + x0;
                    float4 m0 = *reinterpret_cast<const float4*>(rp);
                    float4 m1 = *reinterpret_cast<const float4*>(rp + 4);
                    r[1] = m0.x; r[2] = m0.y; r[3] = m0.z; r[4] = m0.w;
                    r[5] = m1.x; r[6] = m1.y; r[7] = m1.z; r[8] = m1.w;
                    r[0] = (x0 > 0)  ? rp[-1] : 0.f;
                    r[9] = (x0 < 24) ? rp[8]  : 0.f;
                } else {
                    #pragma unroll
                    for (int t = 0; t < 10; t++) r[t] = 0.f;
                }
                #pragma unroll
                for (int co = 0; co < COPB; co++) {
                    const float* wp = &swt[(co*CIN + ci)*27 + kz*9 + ky*3];
                    const float w0 = wp[0], w1 = wp[1], w2 = wp[2];
                    #pragma unroll
                    for (int xi = 0; xi < 8; xi++)
                        acc[co][xi] = fmaf(w0, r[xi],
                                      fmaf(w1, r[xi+1],
                                      fmaf(w2, r[xi+2], acc[co][xi])));
                }
            }
        }
    }

    const float a = PRELU ? alpha[0] : 0.f;
    #pragma unroll
    for (int co = 0; co < COPB; co++) {
        const int ch = cg*COPB + co;
        const float bv = bias[ch];
        float* op = out + ((size_t)(b*out_ct + ch) << 15) + (z << 10) + (y << 5) + x0;
        #pragma unroll
        for (int xi = 0; xi < 8; xi++) {
            float rr = acc[co][xi] + bv;
            if (PRELU) rr = rr >= 0.f ? rr : a * rr;
            if (RES) {
                float nv = op[xi] + rr;
                op[xi] = nv;
                if (WRITE_F && ch == 1)
                    g_f[(size_t)b*NV + ((size_t)(x0 + xi) << 10) + ((size_t)y << 5) + z] = nv;
            } else {
                op[xi] = rr;
            }
        }
    }
}

// ---------------------------------------------------------------------------
// conv2 (32->32) via wmma tf32 in CANONICAL layouts: A row_major, B col_major.
// Exact 3-way tf32 split on both operands (hi+mid+lo == fp32), 6 mma terms.
// Block = 128 threads (4 warps) = (4 y-rows, z-plane, b).
// M = 128 spatial (m = ry*32 + x), N = 32 co, K = 32 (27 taps zero-padded).
// A built per-ci as im2col in smem, row-major [m][k] stride 36.
// B loaded straight from global [ci][n][k] arrays, ldm = 32.
// ---------------------------------------------------------------------------
__global__ void __launch_bounds__(128)
conv2_wmma_kernel(const float* __restrict__ in,
                  const float* __restrict__ whi, const float* __restrict__ wmid,
                  const float* __restrict__ wlo,
                  const float* __restrict__ bias,
                  const float* __restrict__ alpha,
                  float* __restrict__ out) {
    __shared__ float tile[3*6*36];          // [kz][row(6)][col(36, 34 used)]
    __shared__ float Abuf[128*36];          // A: [m][k(36pad, 32 used)]; C: [m][n(36pad)]

    const int b  = blockIdx.z;
    const int z  = blockIdx.y;
    const int y0 = blockIdx.x * 4;
    const int tid  = threadIdx.x;
    const int warp = tid >> 5;
    const int ry = tid >> 5;                // y offset 0..3 of this thread's m-row
    const int x  = tid & 31;

    // zero the padded k cols (27..31) of every A row once
    #pragma unroll
    for (int k = 27; k < 32; k++) Abuf[tid*36 + k] = 0.f;

    wmma::fragment<wmma::accumulator, 16, 16, 8, float> acc[2][2];
    #pragma unroll
    for (int mt = 0; mt < 2; mt++)
        #pragma unroll
        for (int nt = 0; nt < 2; nt++) wmma::fill_fragment(acc[mt][nt], 0.f);

    for (int ci = 0; ci < 32; ci++) {
        __syncthreads();                    // prior A/tile reads done
        const float* inc = in + ((size_t)(b*32 + ci) << 15);
        for (int i = tid; i < 3*6*34; i += 128) {
            int kz = i / 204; int rem = i - kz*204;
            int r  = rem / 34, c = rem - r*34;
            int zz = z - 1 + kz, yy = y0 - 1 + r, xx = c - 1;
            float v = 0.f;
            if ((unsigned)zz < 32u && (unsigned)yy < 32u && (unsigned)xx < 32u)
                v = inc[(zz << 10) + (yy << 5) + xx];
            tile[(kz*6 + r)*36 + c] = v;
        }
        __syncthreads();

        // im2col: thread tid owns A row m = tid; fill k cols 0..26
        #pragma unroll
        for (int k = 0; k < 27; k++) {
            const int kz = k / 9, kr = k - kz*9;
            const int ky = kr / 3, kx = kr - ky*3;
            Abuf[tid*36 + k] = tile[(kz*6 + ky + ry)*36 + x + kx];
        }
        __syncthreads();

        const float* wh = whi  + (size_t)ci*1024;   // [n:32][k:32]
        const float* wm = wmid + (size_t)ci*1024;
        const float* wl = wlo  + (size_t)ci*1024;
        #pragma unroll
        for (int kc = 0; kc < 4; kc++) {
            // B col_major: element (k, n) at base[n*32 + k]; base at k-offset kc*8
            wmma::fragment<wmma::matrix_b, 16, 16, 8, wmma::precision::tf32, wmma::col_major> b1[2], b2[2], b3[2];
            #pragma unroll
            for (int nt = 0; nt < 2; nt++) {
                wmma::load_matrix_sync(b1[nt], wh + nt*16*32 + kc*8, 32);
                wmma::load_matrix_sync(b2[nt], wm + nt*16*32 + kc*8, 32);
                wmma::load_matrix_sync(b3[nt], wl + nt*16*32 + kc*8, 32);
            }
            #pragma unroll
            for (int mt = 0; mt < 2; mt++) {
                wmma::fragment<wmma::matrix_a, 16, 16, 8, wmma::precision::tf32, wmma::row_major> a, a1, a2, a3;
                wmma::load_matrix_sync(a, &Abuf[((warp*2 + mt)*16)*36 + kc*8], 36);
                #pragma unroll
                for (int e = 0; e < a.num_elements; e++) {
                    float v = a.x[e];
                    float h = f2tf32f(v);
                    float r = v - h;            // exact
                    float m = f2tf32f(r);
                    a1.x[e] = h;
                    a2.x[e] = m;
                    a3.x[e] = r - m;            // exact, tf32-representable
                }
                #pragma unroll
                for (int nt = 0; nt < 2; nt++) {
                    wmma::mma_sync(acc[mt][nt], a2, b2[nt], acc[mt][nt]);  // ~2^-22
                    wmma::mma_sync(acc[mt][nt], a1, b3[nt], acc[mt][nt]);  // ~2^-22
                    wmma::mma_sync(acc[mt][nt], a3, b1[nt], acc[mt][nt]);  // ~2^-22
                    wmma::mma_sync(acc[mt][nt], a1, b2[nt], acc[mt][nt]);  // ~2^-11
                    wmma::mma_sync(acc[mt][nt], a2, b1[nt], acc[mt][nt]);  // ~2^-11
                    wmma::mma_sync(acc[mt][nt], a1, b1[nt], acc[mt][nt]);  // main
                }
            }
        }
    }

    // C epilogue through smem (reuse Abuf as [m][n] stride 36)
    __syncthreads();
    #pragma unroll
    for (int mt = 0; mt < 2; mt++)
        #pragma unroll
        for (int nt = 0; nt < 2; nt++)
            wmma::store_matrix_sync(&Abuf[((warp*2 + mt)*16)*36 + nt*16],
                                    acc[mt][nt], 36, wmma::mem_row_major);
    __syncthreads();

    const float aP = alpha[0];
    const int y = y0 + ry;
    const size_t sp = ((size_t)z << 10) + ((size_t)y << 5) + x;
    #pragma unroll
    for (int ch = 0; ch < 32; ch++) {
        float v = Abuf[tid*36 + ch] + bias[ch];
        v = v >= 0.f ? v : aP * v;
        out[(((size_t)(b*32 + ch)) << 15) + sp] = v;
    }
}

// ---------------------------------------------------------------------------
// Output: primal channel 0
// ---------------------------------------------------------------------------
__global__ void out_kernel(float* __restrict__ out) {
    int i = blockIdx.x * blockDim.x + threadIdx.x;
    if (i >= BB*NV) return;
    int b = i / NV, v = i % NV;
    out[i] = g_y3d[(size_t)b*6*NV + v];
}

// ---------------------------------------------------------------------------
extern "C" void kernel_launch(void* const* d_in, const int* in_sizes, int n_in,
                              void* d_out, int out_size) {
    (void)in_sizes; (void)n_in; (void)out_size;
    const float* dual   = (const float*)d_in[0];
    const float* primal = (const float*)d_in[1];
    const float* g      = (const float*)d_in[2];
    const float* An     = (const float*)d_in[3];
    const float* A      = (const float*)d_in[4];
    const float* dw1 = (const float*)d_in[5];  const float* db1 = (const float*)d_in[6];
    const float* da1 = (const float*)d_in[7];
    const float* dw2 = (const float*)d_in[8];  const float* db2 = (const float*)d_in[9];
    const float* da2 = (const float*)d_in[10];
    const float* dw3 = (const float*)d_in[11]; const float* db3 = (const float*)d_in[12];
    const float* pw1 = (const float*)d_in[13]; const float* pb1 = (const float*)d_in[14];
    const float* pa1 = (const float*)d_in[15];
    const float* pw2 = (const float*)d_in[16]; const float* pb2 = (const float*)d_in[17];
    const float* pa2 = (const float*)d_in[18];
    const float* pw3 = (const float*)d_in[19]; const float* pb3 = (const float*)d_in[20];

    float *px2d, *ph2a, *ph2b, *py3d, *ph3a, *ph3b;
    cudaGetSymbolAddress((void**)&px2d, g_x2d);
    cudaGetSymbolAddress((void**)&ph2a, g_h2a);
    cudaGetSymbolAddress((void**)&ph2b, g_h2b);
    cudaGetSymbolAddress((void**)&py3d, g_y3d);
    cudaGetSymbolAddress((void**)&ph3a, g_h3a);
    cudaGetSymbolAddress((void**)&ph3b, g_h3b);
    __half2 *pAn_h, *pA_h;
    cudaGetSymbolAddress((void**)&pAn_h, g_An_h);
    cudaGetSymbolAddress((void**)&pA_h,  g_A_h);
    float *pw2h, *pw2m, *pw2l;
    cudaGetSymbolAddress((void**)&pw2h, g_w2h);
    cudaGetSymbolAddress((void**)&pw2m, g_w2m);
    cudaGetSymbolAddress((void**)&pw2l, g_w2l);

    // one-time per launch: fp16 copies of projection matrices
    const int n4 = NMAT / 4;
    cvt_half_kernel<<<n4/256, 256>>>(An, pAn_h, n4);
    cvt_half_kernel<<<n4/256, 256>>>(A,  pA_h,  n4);

    // one-time per launch: conv2 exact 3-way tf32 weight split
    {
        int t2 = 10*32*32*32;
        precvt_w2_kernel<<<(t2+255)/256, 256>>>(pw2, pw2h, pw2m, pw2l, t2);
    }

    init_kernel<<<(BB*5*NV + 255)/256, 256>>>(dual, g, primal);

    for (int k = 0; k < 10; k++) {
        // --- dual space ---
        evalop1_kernel<<<BB*JJ*DD, 256>>>();

        conv2d_kernel<7, true, false><<<dim3(32, BB), 192>>>(
            px2d, 7, dw1 + (size_t)k*32*7*9, db1 + k*32, da1 + k, ph2a, 32);
        conv2d_kernel<32, true, false><<<dim3(32, BB), 192>>>(
            ph2a, 32, dw2 + (size_t)k*32*32*9, db2 + k*32, da2 + k, ph2b, 32);
        conv2d_kernel<32, false, true><<<dim3(5, BB), 192>>>(
            ph2b, 32, dw3 + (size_t)k*5*32*9, db3 + k*5, nullptr, px2d, 7);

        // --- adjoint ---
        adjoint_kernel<<<BB*NV/8, 256>>>();

        // --- primal space ---
        conv3d_kernel<6, 4, true, false, false><<<dim3(8, 32, BB), 128>>>(
            py3d, 6, pw1 + (size_t)k*32*6*27, pb1 + k*32, pa1 + k, ph3a, 32);
        // conv2 on tensor cores (canonical wmma layouts, exact 3-way split)
        conv2_wmma_kernel<<<dim3(8, 32, BB), 128>>>(
            ph3a, pw2h + (size_t)k*32*32*32, pw2m + (size_t)k*32*32*32,
            pw2l + (size_t)k*32*32*32, pb2 + k*32, pa2 + k, ph3b);
        conv3d_kernel<32, 1, false, true, true><<<dim3(5, 32, BB), 128>>>(
            ph3b, 32, pw3 + (size_t)k*5*32*27, pb3 + k*5, nullptr, py3d, 6);
    }

    out_kernel<<<(BB*NV + 255)/256, 256>>>((float*)d_out);
}

// round 12
// speedup vs baseline: 1.6581x; 1.6581x over previous
#include <cuda_runtime.h>
#include <cuda_fp16.h>
#include <cstdint>

// Problem constants
#define BB   2
#define JJ   24
#define DD   32
#define NV   32768           // 32*32*32
#define PX2D (JJ*DD)         // 768
#define NMAT (BB*JJ*DD*NV)   // 50,331,648 elements in An / A

typedef unsigned long long u64;

// ---------------------------------------------------------------------------
// packed f32x2 helpers
// ---------------------------------------------------------------------------
__device__ __forceinline__ void fma2(u64 &acc, u64 a, u64 b) {
    asm("fma.rn.f32x2 %0, %1, %2, %0;" : "+l"(acc) : "l"(a), "l"(b));
}
__device__ __forceinline__ u64 pack2(float lo, float hi) {
    u64 r; asm("mov.b64 %0, {%1,%2};" : "=l"(r) : "f"(lo), "f"(hi)); return r;
}
__device__ __forceinline__ void unpack2(u64 v, float &lo, float &hi) {
    asm("mov.b64 {%0,%1}, %2;" : "=f"(lo), "=f"(hi) : "l"(v));
}

// ---------------------------------------------------------------------------
// Scratch (device globals; no allocation allowed)
// ---------------------------------------------------------------------------
__device__ float g_x2d[BB*7*PX2D];   // [dual(0..4), evalop1(5), g(6)]
__device__ float g_h2a[BB*32*PX2D];
__device__ float g_h2b[BB*32*PX2D];
__device__ float g_y3d[BB*6*NV];     // [primal(0..4), evalop2(5)]
__device__ float g_h3a[BB*32*NV];
__device__ float g_h3b[BB*32*NV];
__device__ float g_f  [BB*NV];       // Fortran-flattened primal channel 1
__device__ __half g_An_h[NMAT];      // fp16 copy of An (built per launch)
__device__ __half g_A_h [NMAT];      // fp16 copy of A

// ---------------------------------------------------------------------------
// fp32 -> fp16 conversion (streaming)
// ---------------------------------------------------------------------------
__global__ void cvt_half_kernel(const float* __restrict__ src,
                                __half2* __restrict__ dst, int n4) {
    int i = blockIdx.x * blockDim.x + threadIdx.x;
    if (i >= n4) return;
    float4 v = __ldcs(reinterpret_cast<const float4*>(src) + i);
    dst[2*i]   = __floats2half2_rn(v.x, v.y);
    dst[2*i+1] = __floats2half2_rn(v.z, v.w);
}

// ---------------------------------------------------------------------------
// Init: dual -> x2d[0..4], g -> x2d[6], primal -> y3d[0..4], primal ch1 -> g_f
// ---------------------------------------------------------------------------
__global__ void init_kernel(const float* __restrict__ dual,
                            const float* __restrict__ gg,
                            const float* __restrict__ primal) {
    int i = blockIdx.x * blockDim.x + threadIdx.x;
    if (i < BB*5*NV) {
        int b = i / (5*NV); int r = i % (5*NV); int c = r / NV; int v = r % NV;
        g_y3d[(size_t)(b*6 + c)*NV + v] = primal[i];
    }
    if (i < BB*NV) {
        int b = i / NV, v = i % NV;
        int z = v & 31, y = (v >> 5) & 31, x = v >> 10;
        g_f[i] = primal[(size_t)(b*5 + 1)*NV + (z*32 + y)*32 + x];
    }
    if (i < BB*5*PX2D) {
        int b = i / (5*PX2D); int r = i % (5*PX2D); int c = r / PX2D; int p = r % PX2D;
        g_x2d[(size_t)(b*7 + c)*PX2D + p] = dual[i];
    }
    if (i < BB*PX2D) {
        int b = i / PX2D; int p = i % PX2D;
        g_x2d[(size_t)(b*7 + 6)*PX2D + p] = gg[i];
    }
}

// ---------------------------------------------------------------------------
// evalop1[b,j,d] = sum_v An[b,j,d,v] * f[b,v]   (fp16 matrix, fp32 math)
// ---------------------------------------------------------------------------
__global__ void evalop1_kernel() {
    const int row = blockIdx.x;                 // (b*J + j)*D + d
    const int b   = row / PX2D;
    const uint4*  a = reinterpret_cast<const uint4*>(g_An_h) + (size_t)row * (NV/8);
    const float4* f = reinterpret_cast<const float4*>(g_f) + (size_t)b * (NV/4);
    float acc = 0.f;
    #pragma unroll 2
    for (int i = threadIdx.x; i < NV/8; i += 256) {
        uint4 av = __ldcs(a + i);
        float4 f0 = f[2*i], f1 = f[2*i+1];
        float2 p;
        p = __half22float2(*reinterpret_cast<__half2*>(&av.x));
        acc = fmaf(p.x, f0.x, acc); acc = fmaf(p.y, f0.y, acc);
        p = __half22float2(*reinterpret_cast<__half2*>(&av.y));
        acc = fmaf(p.x, f0.z, acc); acc = fmaf(p.y, f0.w, acc);
        p = __half22float2(*reinterpret_cast<__half2*>(&av.z));
        acc = fmaf(p.x, f1.x, acc); acc = fmaf(p.y, f1.y, acc);
        p = __half22float2(*reinterpret_cast<__half2*>(&av.w));
        acc = fmaf(p.x, f1.z, acc); acc = fmaf(p.y, f1.w, acc);
    }
    #pragma unroll
    for (int off = 16; off; off >>= 1) acc += __shfl_down_sync(0xffffffffu, acc, off);
    __shared__ float red[8];
    if ((threadIdx.x & 31) == 0) red[threadIdx.x >> 5] = acc;
    __syncthreads();
    if (threadIdx.x == 0) {
        float s = 0.f;
        #pragma unroll
        for (int i = 0; i < 8; i++) s += red[i];
        g_x2d[(size_t)(b*7 + 5)*PX2D + (row % PX2D)] = s;
    }
}

// ---------------------------------------------------------------------------
// 2D conv 3x3 SAME over (J=24, D=32), register-blocked, float4 weights.
// ---------------------------------------------------------------------------
template<int CIN, bool PRELU, bool RES>
__global__ void __launch_bounds__(192)
conv2d_kernel(const float* __restrict__ in, int in_ct,
              const float* __restrict__ w,
              const float* __restrict__ bias,
              const float* __restrict__ alpha,
              float* __restrict__ out, int out_ct) {
    __shared__ float4 swt4[CIN*3];
    const int co = blockIdx.x;
    const int b  = blockIdx.y;
    const int tid = threadIdx.x;
    {
        float* swts = reinterpret_cast<float*>(swt4);
        for (int i = tid; i < CIN*9; i += 192)
            swts[(i/3)*4 + (i%3)] = w[co*CIN*9 + i];
    }
    __syncthreads();

    const int dg = tid & 7;        // d-chunk 0..7
    const int j  = tid >> 3;       // 0..23
    const int d0 = dg << 2;

    float acc[4] = {0.f, 0.f, 0.f, 0.f};
    const float* xb = in + (size_t)b * in_ct * PX2D;

    for (int ci = 0; ci < CIN; ci++) {
        const float* xc = xb + ci * PX2D;
        #pragma unroll
        for (int kj = 0; kj < 3; kj++) {
            const int jj = j + kj - 1;
            float r[6];
            if (jj >= 0 && jj < JJ) {
                const float* rp = xc + jj*32 + d0;
                float4 m = *reinterpret_cast<const float4*>(rp);
                r[1] = m.x; r[2] = m.y; r[3] = m.z; r[4] = m.w;
                r[0] = (d0 > 0)  ? rp[-1] : 0.f;
                r[5] = (d0 < 28) ? rp[4]  : 0.f;
            } else {
                #pragma unroll
                for (int t = 0; t < 6; t++) r[t] = 0.f;
            }
            const float4 wv = swt4[ci*3 + kj];
            #pragma unroll
            for (int di = 0; di < 4; di++)
                acc[di] = fmaf(wv.x, r[di], fmaf(wv.y, r[di+1], fmaf(wv.z, r[di+2], acc[di])));
        }
    }

    const float a  = PRELU ? alpha[0] : 0.f;
    const float bv = bias[co];
    float* op = out + (size_t)(b*out_ct + co)*PX2D + j*32 + d0;
    #pragma unroll
    for (int di = 0; di < 4; di++) {
        float rr = acc[di] + bv;
        if (PRELU) rr = rr >= 0.f ? rr : a * rr;
        if (RES) op[di] += rr; else op[di] = rr;
    }
}

// ---------------------------------------------------------------------------
// adjoint: back[b,v] = sum_{j,d} A[b,j,v,d] * dual0[b,j,d]   (fp16 matrix)
// ---------------------------------------------------------------------------
__global__ void adjoint_kernel() {
    __shared__ float sd[PX2D];
    const int b  = blockIdx.x / (NV/8);
    const int v0 = (blockIdx.x % (NV/8)) * 8;
    for (int i = threadIdx.x; i < PX2D; i += 256)
        sd[i] = g_x2d[(size_t)(b*7 + 0)*PX2D + i];
    __syncthreads();
    const int wrp = threadIdx.x >> 5, lane = threadIdx.x & 31;
    const int v = v0 + wrp;
    const __half* Ab = g_A_h + (size_t)b * JJ * NV * DD;
    float acc = 0.f;
    #pragma unroll
    for (int j = 0; j < JJ; j++) {
        float av = __half2float(__ldcs(Ab + ((size_t)j*NV + v)*DD + lane));
        acc = fmaf(av, sd[j*DD + lane], acc);
    }
    #pragma unroll
    for (int off = 16; off; off >>= 1) acc += __shfl_down_sync(0xffffffffu, acc, off);
    if (lane == 0) {
        int z = v & 31, y = (v >> 5) & 31, x = v >> 10;
        g_y3d[(size_t)(b*6 + 5)*NV + (z*32 + y)*32 + x] = acc;
    }
}

// ---------------------------------------------------------------------------
// 3D conv 3x3x3 SAME over 32^3, direct-from-global register blocking,
// packed fma.rn.f32x2 (FFMA2) inner loop.
// R3 geometry: block = (co-group, z-plane, b), 128 threads (4 xg x 32 y).
// Thread = 8 x outputs = 4 f32x2 accumulator pairs per COPB channel.
// Even-aligned P pairs come free from the two LDG.128; 5 odd Q pairs packed.
// Weights staged duplicated as (w,w) u64 -> one LDS.64 = packed broadcast.
// WRITE_F: channel-1 residual result also scattered into g_f (Fortran order).
// ---------------------------------------------------------------------------
template<int CIN, int COPB, bool PRELU, bool RES, bool WRITE_F>
__global__ void __launch_bounds__(128)
conv3d_kernel(const float* __restrict__ in, int in_ct,
              const float* __restrict__ w,
              const float* __restrict__ bias,
              const float* __restrict__ alpha,
              float* __restrict__ out, int out_ct) {
    __shared__ u64 swt[COPB*CIN*27];     // duplicated (w,w) pairs
    const int b   = blockIdx.z;
    const int z   = blockIdx.y;
    const int cg  = blockIdx.x;
    const int tid = threadIdx.x;

    for (int i = tid; i < COPB*CIN*27; i += 128) {
        float wv = w[(size_t)cg*COPB*CIN*27 + i];
        swt[i] = pack2(wv, wv);
    }
    __syncthreads();

    const int xg = tid & 3;
    const int y  = tid >> 2;
    const int x0 = xg << 3;

    u64 acc[COPB][4];                    // pairs (x0,x1)..(x6,x7)
    #pragma unroll
    for (int c = 0; c < COPB; c++)
        #pragma unroll
        for (int p = 0; p < 4; p++) acc[c][p] = 0ull;

    for (int ci = 0; ci < CIN; ci++) {
        const float* pc = in + ((size_t)(b*in_ct + ci) << 15);
        #pragma unroll
        for (int kz = 0; kz < 3; kz++) {
            const int zz = z + kz - 1;
            if (zz < 0 || zz >= 32) continue;      // uniform per block
            #pragma unroll
            for (int ky = 0; ky < 3; ky++) {
                const int yy = y + ky - 1;
                float r[10];
                if (yy >= 0 && yy < 32) {
                    const float* rp = pc + ((zz << 5) + yy)*32 + x0;
                    float4 m0 = *reinterpret_cast<const float4*>(rp);
                    float4 m1 = *reinterpret_cast<const float4*>(rp + 4);
                    r[1] = m0.x; r[2] = m0.y; r[3] = m0.z; r[4] = m0.w;
                    r[5] = m1.x; r[6] = m1.y; r[7] = m1.z; r[8] = m1.w;
                    r[0] = (x0 > 0)  ? rp[-1] : 0.f;
                    r[9] = (x0 < 24) ? rp[8]  : 0.f;
                } else {
                    #pragma unroll
                    for (int t = 0; t < 10; t++) r[t] = 0.f;
                }
                // P = odd-start pairs (free from LDG.128 quads),
                // Q = even-start pairs (packed)
                u64 P[4], Q[5];
                P[0] = pack2(r[1], r[2]); P[1] = pack2(r[3], r[4]);
                P[2] = pack2(r[5], r[6]); P[3] = pack2(r[7], r[8]);
                Q[0] = pack2(r[0], r[1]); Q[1] = pack2(r[2], r[3]);
                Q[2] = pack2(r[4], r[5]); Q[3] = pack2(r[6], r[7]);
                Q[4] = pack2(r[8], r[9]);
                #pragma unroll
                for (int co = 0; co < COPB; co++) {
                    const u64* wp = &swt[(co*CIN + ci)*27 + kz*9 + ky*3];
                    const u64 w0 = wp[0], w1 = wp[1], w2 = wp[2];
                    // tap kx=0 (offset -1): even-start pairs Q0..Q3
                    fma2(acc[co][0], w0, Q[0]);
                    fma2(acc[co][1], w0, Q[1]);
                    fma2(acc[co][2], w0, Q[2]);
                    fma2(acc[co][3], w0, Q[3]);
                    // tap kx=1 (offset 0): P0..P3
                    fma2(acc[co][0], w1, P[0]);
                    fma2(acc[co][1], w1, P[1]);
                    fma2(acc[co][2], w1, P[2]);
                    fma2(acc[co][3], w1, P[3]);
                    // tap kx=2 (offset +1): Q1..Q4
                    fma2(acc[co][0], w2, Q[1]);
                    fma2(acc[co][1], w2, Q[2]);
                    fma2(acc[co][2], w2, Q[3]);
                    fma2(acc[co][3], w2, Q[4]);
                }
            }
        }
    }

    const float a = PRELU ? alpha[0] : 0.f;
    #pragma unroll
    for (int co = 0; co < COPB; co++) {
        const int ch = cg*COPB + co;
        const float bv = bias[ch];
        float* op = out + ((size_t)(b*out_ct + ch) << 15) + (z << 10) + (y << 5) + x0;
        #pragma unroll
        for (int p = 0; p < 4; p++) {
            float lo, hi;
            unpack2(acc[co][p], lo, hi);
            float r0 = lo + bv, r1 = hi + bv;
            if (PRELU) {
                r0 = r0 >= 0.f ? r0 : a * r0;
                r1 = r1 >= 0.f ? r1 : a * r1;
            }
            const int xa = x0 + 2*p, xb2 = x0 + 2*p + 1;
            if (RES) {
                float n0 = op[2*p]   + r0;
                float n1 = op[2*p+1] + r1;
                op[2*p]   = n0;
                op[2*p+1] = n1;
                if (WRITE_F && ch == 1) {
                    g_f[(size_t)b*NV + ((size_t)xa  << 10) + ((size_t)y << 5) + z] = n0;
                    g_f[(size_t)b*NV + ((size_t)xb2 << 10) + ((size_t)y << 5) + z] = n1;
                }
            } else {
                op[2*p]   = r0;
                op[2*p+1] = r1;
            }
        }
    }
}

// ---------------------------------------------------------------------------
// Output: primal channel 0
// ---------------------------------------------------------------------------
__global__ void out_kernel(float* __restrict__ out) {
    int i = blockIdx.x * blockDim.x + threadIdx.x;
    if (i >= BB*NV) return;
    int b = i / NV, v = i % NV;
    out[i] = g_y3d[(size_t)b*6*NV + v];
}

// ---------------------------------------------------------------------------
extern "C" void kernel_launch(void* const* d_in, const int* in_sizes, int n_in,
                              void* d_out, int out_size) {
    (void)in_sizes; (void)n_in; (void)out_size;
    const float* dual   = (const float*)d_in[0];
    const float* primal = (const float*)d_in[1];
    const float* g      = (const float*)d_in[2];
    const float* An     = (const float*)d_in[3];
    const float* A      = (const float*)d_in[4];
    const float* dw1 = (const float*)d_in[5];  const float* db1 = (const float*)d_in[6];
    const float* da1 = (const float*)d_in[7];
    const float* dw2 = (const float*)d_in[8];  const float* db2 = (const float*)d_in[9];
    const float* da2 = (const float*)d_in[10];
    const float* dw3 = (const float*)d_in[11]; const float* db3 = (const float*)d_in[12];
    const float* pw1 = (const float*)d_in[13]; const float* pb1 = (const float*)d_in[14];
    const float* pa1 = (const float*)d_in[15];
    const float* pw2 = (const float*)d_in[16]; const float* pb2 = (const float*)d_in[17];
    const float* pa2 = (const float*)d_in[18];
    const float* pw3 = (const float*)d_in[19]; const float* pb3 = (const float*)d_in[20];

    float *px2d, *ph2a, *ph2b, *py3d, *ph3a, *ph3b;
    cudaGetSymbolAddress((void**)&px2d, g_x2d);
    cudaGetSymbolAddress((void**)&ph2a, g_h2a);
    cudaGetSymbolAddress((void**)&ph2b, g_h2b);
    cudaGetSymbolAddress((void**)&py3d, g_y3d);
    cudaGetSymbolAddress((void**)&ph3a, g_h3a);
    cudaGetSymbolAddress((void**)&ph3b, g_h3b);
    __half2 *pAn_h, *pA_h;
    cudaGetSymbolAddress((void**)&pAn_h, g_An_h);
    cudaGetSymbolAddress((void**)&pA_h,  g_A_h);

    // one-time per launch: fp16 copies of projection matrices
    const int n4 = NMAT / 4;
    cvt_half_kernel<<<n4/256, 256>>>(An, pAn_h, n4);
    cvt_half_kernel<<<n4/256, 256>>>(A,  pA_h,  n4);

    init_kernel<<<(BB*5*NV + 255)/256, 256>>>(dual, g, primal);

    for (int k = 0; k < 10; k++) {
        // --- dual space ---
        evalop1_kernel<<<BB*JJ*DD, 256>>>();

        conv2d_kernel<7, true, false><<<dim3(32, BB), 192>>>(
            px2d, 7, dw1 + (size_t)k*32*7*9, db1 + k*32, da1 + k, ph2a, 32);
        conv2d_kernel<32, true, false><<<dim3(32, BB), 192>>>(
            ph2a, 32, dw2 + (size_t)k*32*32*9, db2 + k*32, da2 + k, ph2b, 32);
        conv2d_kernel<32, false, true><<<dim3(5, BB), 192>>>(
            ph2b, 32, dw3 + (size_t)k*5*32*9, db3 + k*5, nullptr, px2d, 7);

        // --- adjoint ---
        adjoint_kernel<<<BB*NV/8, 256>>>();

        // --- primal space (FFMA2 conv3d, R3 geometry) ---
        conv3d_kernel<6, 4, true, false, false><<<dim3(8, 32, BB), 128>>>(
            py3d, 6, pw1 + (size_t)k*32*6*27, pb1 + k*32, pa1 + k, ph3a, 32);
        conv3d_kernel<32, 4, true, false, false><<<dim3(8, 32, BB), 128>>>(
            ph3a, 32, pw2 + (size_t)k*32*32*27, pb2 + k*32, pa2 + k, ph3b, 32);
        conv3d_kernel<32, 1, false, true, true><<<dim3(5, 32, BB), 128>>>(
            ph3b, 32, pw3 + (size_t)k*5*32*27, pb3 + k*5, nullptr, py3d, 6);
    }

    out_kernel<<<(BB*NV + 255)/256, 256>>>((float*)d_out);
}

// round 14
// speedup vs baseline: 1.6922x; 1.0205x over previous
#include <cuda_runtime.h>
#include <cuda_fp16.h>
#include <cstdint>

// Problem constants
#define BB   2
#define JJ   24
#define DD   32
#define NV   32768           // 32*32*32
#define PX2D (JJ*DD)         // 768
#define NMAT (BB*JJ*DD*NV)   // 50,331,648 elements in An / A

// ---------------------------------------------------------------------------
// Scratch (device globals; no allocation allowed)
// ---------------------------------------------------------------------------
__device__ float g_x2d[BB*7*PX2D];   // [dual(0..4), evalop1(5), g(6)]
__device__ float g_h2a[BB*32*PX2D];
__device__ float g_h2b[BB*32*PX2D];
__device__ float g_y3d[BB*6*NV];     // [primal(0..4), evalop2(5)]
__device__ float g_h3a[BB*32*NV];
__device__ float g_h3b[BB*32*NV];
__device__ float g_f  [BB*NV];       // Fortran-flattened primal channel 1
__device__ __half g_An_h[NMAT];      // fp16 copy of An (built per launch)
__device__ __half g_A_h [NMAT];      // fp16 copy of A

// ---------------------------------------------------------------------------
// fp32 -> fp16 conversion (streaming)
// ---------------------------------------------------------------------------
__global__ void cvt_half_kernel(const float* __restrict__ src,
                                __half2* __restrict__ dst, int n4) {
    int i = blockIdx.x * blockDim.x + threadIdx.x;
    if (i >= n4) return;
    float4 v = __ldcs(reinterpret_cast<const float4*>(src) + i);
    dst[2*i]   = __floats2half2_rn(v.x, v.y);
    dst[2*i+1] = __floats2half2_rn(v.z, v.w);
}

// ---------------------------------------------------------------------------
// Init: dual -> x2d[0..4], g -> x2d[6], primal -> y3d[0..4], primal ch1 -> g_f
// ---------------------------------------------------------------------------
__global__ void init_kernel(const float* __restrict__ dual,
                            const float* __restrict__ gg,
                            const float* __restrict__ primal) {
    int i = blockIdx.x * blockDim.x + threadIdx.x;
    if (i < BB*5*NV) {
        int b = i / (5*NV); int r = i % (5*NV); int c = r / NV; int v = r % NV;
        g_y3d[(size_t)(b*6 + c)*NV + v] = primal[i];
    }
    if (i < BB*NV) {
        int b = i / NV, v = i % NV;
        int z = v & 31, y = (v >> 5) & 31, x = v >> 10;
        g_f[i] = primal[(size_t)(b*5 + 1)*NV + (z*32 + y)*32 + x];
    }
    if (i < BB*5*PX2D) {
        int b = i / (5*PX2D); int r = i % (5*PX2D); int c = r / PX2D; int p = r % PX2D;
        g_x2d[(size_t)(b*7 + c)*PX2D + p] = dual[i];
    }
    if (i < BB*PX2D) {
        int b = i / PX2D; int p = i % PX2D;
        g_x2d[(size_t)(b*7 + 6)*PX2D + p] = gg[i];
    }
}

// ---------------------------------------------------------------------------
// evalop1[b,j,d] = sum_v An[b,j,d,v] * f[b,v]   (fp16 matrix, fp32 math)
// ---------------------------------------------------------------------------
__global__ void evalop1_kernel() {
    const int row = blockIdx.x;                 // (b*J + j)*D + d
    const int b   = row / PX2D;
    const uint4*  a = reinterpret_cast<const uint4*>(g_An_h) + (size_t)row * (NV/8);
    const float4* f = reinterpret_cast<const float4*>(g_f) + (size_t)b * (NV/4);
    float acc = 0.f;
    #pragma unroll 2
    for (int i = threadIdx.x; i < NV/8; i += 256) {
        uint4 av = __ldcs(a + i);
        float4 f0 = f[2*i], f1 = f[2*i+1];
        float2 p;
        p = __half22float2(*reinterpret_cast<__half2*>(&av.x));
        acc = fmaf(p.x, f0.x, acc); acc = fmaf(p.y, f0.y, acc);
        p = __half22float2(*reinterpret_cast<__half2*>(&av.y));
        acc = fmaf(p.x, f0.z, acc); acc = fmaf(p.y, f0.w, acc);
        p = __half22float2(*reinterpret_cast<__half2*>(&av.z));
        acc = fmaf(p.x, f1.x, acc); acc = fmaf(p.y, f1.y, acc);
        p = __half22float2(*reinterpret_cast<__half2*>(&av.w));
        acc = fmaf(p.x, f1.z, acc); acc = fmaf(p.y, f1.w, acc);
    }
    #pragma unroll
    for (int off = 16; off; off >>= 1) acc += __shfl_down_sync(0xffffffffu, acc, off);
    __shared__ float red[8];
    if ((threadIdx.x & 31) == 0) red[threadIdx.x >> 5] = acc;
    __syncthreads();
    if (threadIdx.x == 0) {
        float s = 0.f;
        #pragma unroll
        for (int i = 0; i < 8; i++) s += red[i];
        g_x2d[(size_t)(b*7 + 5)*PX2D + (row % PX2D)] = s;
    }
}

// ---------------------------------------------------------------------------
// 2D conv 3x3 SAME over (J=24, D=32), register-blocked, float4 weights.
// ---------------------------------------------------------------------------
template<int CIN, bool PRELU, bool RES>
__global__ void __launch_bounds__(192)
conv2d_kernel(const float* __restrict__ in, int in_ct,
              const float* __restrict__ w,
              const float* __restrict__ bias,
              const float* __restrict__ alpha,
              float* __restrict__ out, int out_ct) {
    __shared__ float4 swt4[CIN*3];
    const int co = blockIdx.x;
    const int b  = blockIdx.y;
    const int tid = threadIdx.x;
    {
        float* swts = reinterpret_cast<float*>(swt4);
        for (int i = tid; i < CIN*9; i += 192)
            swts[(i/3)*4 + (i%3)] = w[co*CIN*9 + i];
    }
    __syncthreads();

    const int dg = tid & 7;        // d-chunk 0..7
    const int j  = tid >> 3;       // 0..23
    const int d0 = dg << 2;

    float acc[4] = {0.f, 0.f, 0.f, 0.f};
    const float* xb = in + (size_t)b * in_ct * PX2D;

    for (int ci = 0; ci < CIN; ci++) {
        const float* xc = xb + ci * PX2D;
        #pragma unroll
        for (int kj = 0; kj < 3; kj++) {
            const int jj = j + kj - 1;
            float r[6];
            if (jj >= 0 && jj < JJ) {
                const float* rp = xc + jj*32 + d0;
                float4 m = *reinterpret_cast<const float4*>(rp);
                r[1] = m.x; r[2] = m.y; r[3] = m.z; r[4] = m.w;
                r[0] = (d0 > 0)  ? rp[-1] : 0.f;
                r[5] = (d0 < 28) ? rp[4]  : 0.f;
            } else {
                #pragma unroll
                for (int t = 0; t < 6; t++) r[t] = 0.f;
            }
            const float4 wv = swt4[ci*3 + kj];
            #pragma unroll
            for (int di = 0; di < 4; di++)
                acc[di] = fmaf(wv.x, r[di], fmaf(wv.y, r[di+1], fmaf(wv.z, r[di+2], acc[di])));
        }
    }

    const float a  = PRELU ? alpha[0] : 0.f;
    const float bv = bias[co];
    float* op = out + (size_t)(b*out_ct + co)*PX2D + j*32 + d0;
    #pragma unroll
    for (int di = 0; di < 4; di++) {
        float rr = acc[di] + bv;
        if (PRELU) rr = rr >= 0.f ? rr : a * rr;
        if (RES) op[di] += rr; else op[di] = rr;
    }
}

// ---------------------------------------------------------------------------
// adjoint: back[b,v] = sum_{j,d} A[b,j,v,d] * dual0[b,j,d]   (fp16 matrix)
// ---------------------------------------------------------------------------
__global__ void adjoint_kernel() {
    __shared__ float sd[PX2D];
    const int b  = blockIdx.x / (NV/8);
    const int v0 = (blockIdx.x % (NV/8)) * 8;
    for (int i = threadIdx.x; i < PX2D; i += 256)
        sd[i] = g_x2d[(size_t)(b*7 + 0)*PX2D + i];
    __syncthreads();
    const int wrp = threadIdx.x >> 5, lane = threadIdx.x & 31;
    const int v = v0 + wrp;
    const __half* Ab = g_A_h + (size_t)b * JJ * NV * DD;
    float acc = 0.f;
    #pragma unroll
    for (int j = 0; j < JJ; j++) {
        float av = __half2float(__ldcs(Ab + ((size_t)j*NV + v)*DD + lane));
        acc = fmaf(av, sd[j*DD + lane], acc);
    }
    #pragma unroll
    for (int off = 16; off; off >>= 1) acc += __shfl_down_sync(0xffffffffu, acc, off);
    if (lane == 0) {
        int z = v & 31, y = (v >> 5) & 31, x = v >> 10;
        g_y3d[(size_t)(b*6 + 5)*NV + (z*32 + y)*32 + x] = acc;
    }
}

// ---------------------------------------------------------------------------
// row load macro for conv3d: 10 floats (8 outputs + 2 halo) or zeros
// ---------------------------------------------------------------------------
#define LOADROW(dst, pc, t)                                              \
    do {                                                                  \
        if (tval[t]) {                                                    \
            const float* rp = (pc) + toff[t];                             \
            float4 m0 = *reinterpret_cast<const float4*>(rp);             \
            float4 m1 = *reinterpret_cast<const float4*>(rp + 4);         \
            dst[1] = m0.x; dst[2] = m0.y; dst[3] = m0.z; dst[4] = m0.w;   \
            dst[5] = m1.x; dst[6] = m1.y; dst[7] = m1.z; dst[8] = m1.w;   \
            dst[0] = lguard ? rp[-1] : 0.f;                               \
            dst[9] = rguard ? rp[8]  : 0.f;                               \
        } else {                                                          \
            _Pragma("unroll")                                             \
            for (int _i = 0; _i < 10; _i++) dst[_i] = 0.f;                \
        }                                                                 \
    } while (0)

// ---------------------------------------------------------------------------
// 3D conv 3x3x3 SAME over 32^3, direct-from-global register blocking with a
// 1-deep software prefetch pipeline: the next tap-row's LDGs are issued
// before the current row's 96 FMAs, hiding ~250cyc of L2 latency.
// R3 geometry: block = (co-group, z-plane, b), 128 threads (4 xg x 32 y).
// Thread = 8 consecutive x outputs for COPB output channels.
// Out-of-bounds taps contribute exact-zero rows (fma(w,0,acc)==acc).
// WRITE_F: channel-1 residual result also scattered into g_f (Fortran order).
// ---------------------------------------------------------------------------
template<int CIN, int COPB, bool PRELU, bool RES, bool WRITE_F>
__global__ void __launch_bounds__(128)
conv3d_kernel(const float* __restrict__ in, int in_ct,
              const float* __restrict__ w,
              const float* __restrict__ bias,
              const float* __restrict__ alpha,
              float* __restrict__ out, int out_ct) {
    __shared__ float swt[COPB*CIN*27];
    const int b   = blockIdx.z;
    const int z   = blockIdx.y;
    const int cg  = blockIdx.x;
    const int tid = threadIdx.x;

    for (int i = tid; i < COPB*CIN*27; i += 128)
        swt[i] = w[(size_t)cg*COPB*CIN*27 + i];
    __syncthreads();

    const int xg = tid & 3;
    const int y  = tid >> 2;
    const int x0 = xg << 3;
    const bool lguard = (x0 > 0);
    const bool rguard = (x0 < 24);

    // ci-invariant tap offsets + validity
    int  toff[9];
    bool tval[9];
    #pragma unroll
    for (int t = 0; t < 9; t++) {
        const int kz = t / 3, ky = t % 3;
        const int zz = z + kz - 1, yy = y + ky - 1;
        tval[t] = ((unsigned)zz < 32u) && ((unsigned)yy < 32u);
        toff[t] = ((zz << 5) + yy)*32 + x0;
    }

    float acc[COPB][8];
    #pragma unroll
    for (int c = 0; c < COPB; c++)
        #pragma unroll
        for (int xi = 0; xi < 8; xi++) acc[c][xi] = 0.f;

    float cur[10], nxt[10];
    {
        const float* pc = in + ((size_t)(b*in_ct) << 15);
        LOADROW(cur, pc, 0);
    }

    #pragma unroll 1
    for (int ci = 0; ci < CIN; ci++) {
        const float* pc  = in + ((size_t)(b*in_ct + ci) << 15);
        const int cin_n  = (ci + 1 < CIN) ? (ci + 1) : ci;
        const float* pcn = in + ((size_t)(b*in_ct + cin_n) << 15);
        #pragma unroll
        for (int t = 0; t < 9; t++) {
            // prefetch the next row while computing the current one
            if (t < 8) { LOADROW(nxt, pc, t + 1); }
            else       { LOADROW(nxt, pcn, 0); }
            #pragma unroll
            for (int co = 0; co < COPB; co++) {
                const float* wp = &swt[(co*CIN + ci)*27 + t*3];
                const float w0 = wp[0], w1 = wp[1], w2 = wp[2];
                #pragma unroll
                for (int xi = 0; xi < 8; xi++)
                    acc[co][xi] = fmaf(w0, cur[xi],
                                  fmaf(w1, cur[xi+1],
                                  fmaf(w2, cur[xi+2], acc[co][xi])));
            }
            #pragma unroll
            for (int i = 0; i < 10; i++) cur[i] = nxt[i];
        }
    }

    const float a = PRELU ? alpha[0] : 0.f;
    #pragma unroll
    for (int co = 0; co < COPB; co++) {
        const int ch = cg*COPB + co;
        const float bv = bias[ch];
        float* op = out + ((size_t)(b*out_ct + ch) << 15) + (z << 10) + (y << 5) + x0;
        #pragma unroll
        for (int xi = 0; xi < 8; xi++) {
            float rr = acc[co][xi] + bv;
            if (PRELU) rr = rr >= 0.f ? rr : a * rr;
            if (RES) {
                float nv = op[xi] + rr;
                op[xi] = nv;
                if (WRITE_F && ch == 1)
                    g_f[(size_t)b*NV + ((size_t)(x0 + xi) << 10) + ((size_t)y << 5) + z] = nv;
            } else {
                op[xi] = rr;
            }
        }
    }
}

// ---------------------------------------------------------------------------
// Output: primal channel 0
// ---------------------------------------------------------------------------
__global__ void out_kernel(float* __restrict__ out) {
    int i = blockIdx.x * blockDim.x + threadIdx.x;
    if (i >= BB*NV) return;
    int b = i / NV, v = i % NV;
    out[i] = g_y3d[(size_t)b*6*NV + v];
}

// ---------------------------------------------------------------------------
extern "C" void kernel_launch(void* const* d_in, const int* in_sizes, int n_in,
                              void* d_out, int out_size) {
    (void)in_sizes; (void)n_in; (void)out_size;
    const float* dual   = (const float*)d_in[0];
    const float* primal = (const float*)d_in[1];
    const float* g      = (const float*)d_in[2];
    const float* An     = (const float*)d_in[3];
    const float* A      = (const float*)d_in[4];
    const float* dw1 = (const float*)d_in[5];  const float* db1 = (const float*)d_in[6];
    const float* da1 = (const float*)d_in[7];
    const float* dw2 = (const float*)d_in[8];  const float* db2 = (const float*)d_in[9];
    const float* da2 = (const float*)d_in[10];
    const float* dw3 = (const float*)d_in[11]; const float* db3 = (const float*)d_in[12];
    const float* pw1 = (const float*)d_in[13]; const float* pb1 = (const float*)d_in[14];
    const float* pa1 = (const float*)d_in[15];
    const float* pw2 = (const float*)d_in[16]; const float* pb2 = (const float*)d_in[17];
    const float* pa2 = (const float*)d_in[18];
    const float* pw3 = (const float*)d_in[19]; const float* pb3 = (const float*)d_in[20];

    float *px2d, *ph2a, *ph2b, *py3d, *ph3a, *ph3b;
    cudaGetSymbolAddress((void**)&px2d, g_x2d);
    cudaGetSymbolAddress((void**)&ph2a, g_h2a);
    cudaGetSymbolAddress((void**)&ph2b, g_h2b);
    cudaGetSymbolAddress((void**)&py3d, g_y3d);
    cudaGetSymbolAddress((void**)&ph3a, g_h3a);
    cudaGetSymbolAddress((void**)&ph3b, g_h3b);
    __half2 *pAn_h, *pA_h;
    cudaGetSymbolAddress((void**)&pAn_h, g_An_h);
    cudaGetSymbolAddress((void**)&pA_h,  g_A_h);

    // one-time per launch: fp16 copies of projection matrices
    const int n4 = NMAT / 4;
    cvt_half_kernel<<<n4/256, 256>>>(An, pAn_h, n4);
    cvt_half_kernel<<<n4/256, 256>>>(A,  pA_h,  n4);

    init_kernel<<<(BB*5*NV + 255)/256, 256>>>(dual, g, primal);

    for (int k = 0; k < 10; k++) {
        // --- dual space ---
        evalop1_kernel<<<BB*JJ*DD, 256>>>();

        conv2d_kernel<7, true, false><<<dim3(32, BB), 192>>>(
            px2d, 7, dw1 + (size_t)k*32*7*9, db1 + k*32, da1 + k, ph2a, 32);
        conv2d_kernel<32, true, false><<<dim3(32, BB), 192>>>(
            ph2a, 32, dw2 + (size_t)k*32*32*9, db2 + k*32, da2 + k, ph2b, 32);
        conv2d_kernel<32, false, true><<<dim3(5, BB), 192>>>(
            ph2b, 32, dw3 + (size_t)k*5*32*9, db3 + k*5, nullptr, px2d, 7);

        // --- adjoint ---
        adjoint_kernel<<<BB*NV/8, 256>>>();

        // --- primal space (prefetch-pipelined scalar conv3d) ---
        conv3d_kernel<6, 4, true, false, false><<<dim3(8, 32, BB), 128>>>(
            py3d, 6, pw1 + (size_t)k*32*6*27, pb1 + k*32, pa1 + k, ph3a, 32);
        conv3d_kernel<32, 4, true, false, false><<<dim3(8, 32, BB), 128>>>(
            ph3a, 32, pw2 + (size_t)k*32*32*27, pb2 + k*32, pa2 + k, ph3b, 32);
        conv3d_kernel<32, 1, false, true, true><<<dim3(5, 32, BB), 128>>>(
            ph3b, 32, pw3 + (size_t)k*5*32*27, pb3 + k*5, nullptr, py3d, 6);
    }

    out_kernel<<<(BB*NV + 255)/256, 256>>>((float*)d_out);
}

// round 15
// speedup vs baseline: 1.8197x; 1.0754x over previous
#include <cuda_runtime.h>
#include <cuda_fp16.h>
#include <cstdint>

// Problem constants
#define BB   2
#define JJ   24
#define DD   32
#define NV   32768           // 32*32*32
#define PX2D (JJ*DD)         // 768
#define NMAT (BB*JJ*DD*NV)   // 50,331,648 elements in An / A

// ---------------------------------------------------------------------------
// Scratch (device globals; no allocation allowed)
// ---------------------------------------------------------------------------
__device__ float g_x2d[BB*7*PX2D];   // [dual(0..4), evalop1(5), g(6)]
__device__ float g_h2a[BB*32*PX2D];
__device__ float g_h2b[BB*32*PX2D];
__device__ float g_y3d[BB*6*NV];     // [primal(0..4), evalop2(5)]
__device__ float g_h3a[BB*32*NV];
__device__ float g_h3b[BB*32*NV];
__device__ float g_f  [BB*NV];       // Fortran-flattened primal channel 1
__device__ __half g_An_h[NMAT];      // fp16 copy of An (built per launch)
__device__ __half g_A_h [NMAT];      // fp16 copy of A

// ---------------------------------------------------------------------------
// fp32 -> fp16 conversion (both matrices in one launch; blockIdx.y selects)
// ---------------------------------------------------------------------------
__global__ void cvt_half_kernel(const float* __restrict__ s0,
                                const float* __restrict__ s1,
                                __half2* __restrict__ d0,
                                __half2* __restrict__ d1, int n4) {
    int i = blockIdx.x * blockDim.x + threadIdx.x;
    if (i >= n4) return;
    const float* src = blockIdx.y ? s1 : s0;
    __half2*     dst = blockIdx.y ? d1 : d0;
    float4 v = __ldcs(reinterpret_cast<const float4*>(src) + i);
    dst[2*i]   = __floats2half2_rn(v.x, v.y);
    dst[2*i+1] = __floats2half2_rn(v.z, v.w);
}

// ---------------------------------------------------------------------------
// Init: dual -> x2d[0..4], g -> x2d[6], primal -> y3d[0..4]
// ---------------------------------------------------------------------------
__global__ void init_kernel(const float* __restrict__ dual,
                            const float* __restrict__ gg,
                            const float* __restrict__ primal) {
    int i = blockIdx.x * blockDim.x + threadIdx.x;
    if (i < BB*5*NV) {
        int b = i / (5*NV); int r = i % (5*NV); int c = r / NV; int v = r % NV;
        g_y3d[(size_t)(b*6 + c)*NV + v] = primal[i];
    }
    if (i < BB*5*PX2D) {
        int b = i / (5*PX2D); int r = i % (5*PX2D); int c = r / PX2D; int p = r % PX2D;
        g_x2d[(size_t)(b*7 + c)*PX2D + p] = dual[i];
    }
    if (i < BB*PX2D) {
        int b = i / PX2D; int p = i % PX2D;
        g_x2d[(size_t)(b*7 + 6)*PX2D + p] = gg[i];
    }
}

// ---------------------------------------------------------------------------
// Fortran-order gather: f[b, x*1024+y*32+z] = primal_ch1[b, z, y, x]
// ---------------------------------------------------------------------------
__global__ void gather_f_kernel() {
    int i = blockIdx.x * blockDim.x + threadIdx.x;
    if (i >= BB*NV) return;
    int b = i / NV, v = i % NV;
    int z = v & 31, y = (v >> 5) & 31, x = v >> 10;
    g_f[i] = g_y3d[(size_t)(b*6 + 1)*NV + (z*32 + y)*32 + x];
}

// ---------------------------------------------------------------------------
// evalop1[b,j,d] = sum_v An[b,j,d,v] * f[b,v]   (fp16 matrix, fp32 math)
// 4 rows per block: one f load feeds 4 accumulators -> 4x less f L2 traffic.
// Per-row v-order identical to the single-row version (bitwise-stable sums).
// ---------------------------------------------------------------------------
__global__ void evalop1_kernel() {
    const int rg = blockIdx.x;                  // row group (4 rows), 384 total
    const int b  = rg / (PX2D/4);
    const uint4*  a0 = reinterpret_cast<const uint4*>(g_An_h) + (size_t)(rg*4) * (NV/8);
    const float4* f  = reinterpret_cast<const float4*>(g_f) + (size_t)b * (NV/4);
    float acc[4] = {0.f, 0.f, 0.f, 0.f};
    for (int i = threadIdx.x; i < NV/8; i += 256) {
        float4 f0 = f[2*i], f1 = f[2*i+1];
        #pragma unroll
        for (int r = 0; r < 4; r++) {
            uint4 av = __ldcs(a0 + (size_t)r*(NV/8) + i);
            float2 p;
            p = __half22float2(*reinterpret_cast<__half2*>(&av.x));
            acc[r] = fmaf(p.x, f0.x, acc[r]); acc[r] = fmaf(p.y, f0.y, acc[r]);
            p = __half22float2(*reinterpret_cast<__half2*>(&av.y));
            acc[r] = fmaf(p.x, f0.z, acc[r]); acc[r] = fmaf(p.y, f0.w, acc[r]);
            p = __half22float2(*reinterpret_cast<__half2*>(&av.z));
            acc[r] = fmaf(p.x, f1.x, acc[r]); acc[r] = fmaf(p.y, f1.y, acc[r]);
            p = __half22float2(*reinterpret_cast<__half2*>(&av.w));
            acc[r] = fmaf(p.x, f1.z, acc[r]); acc[r] = fmaf(p.y, f1.w, acc[r]);
        }
    }
    #pragma unroll
    for (int r = 0; r < 4; r++)
        #pragma unroll
        for (int off = 16; off; off >>= 1)
            acc[r] += __shfl_down_sync(0xffffffffu, acc[r], off);
    __shared__ float red[8][4];
    if ((threadIdx.x & 31) == 0) {
        #pragma unroll
        for (int r = 0; r < 4; r++) red[threadIdx.x >> 5][r] = acc[r];
    }
    __syncthreads();
    if (threadIdx.x < 4) {
        float s = 0.f;
        #pragma unroll
        for (int i = 0; i < 8; i++) s += red[i][threadIdx.x];
        const int row = rg*4 + threadIdx.x;
        g_x2d[(size_t)(b*7 + 5)*PX2D + (row % PX2D)] = s;
    }
}

// ---------------------------------------------------------------------------
// 2D conv 3x3 SAME over (J=24, D=32), register-blocked, float4 weights.
// ---------------------------------------------------------------------------
template<int CIN, bool PRELU, bool RES>
__global__ void __launch_bounds__(192)
conv2d_kernel(const float* __restrict__ in, int in_ct,
              const float* __restrict__ w,
              const float* __restrict__ bias,
              const float* __restrict__ alpha,
              float* __restrict__ out, int out_ct) {
    __shared__ float4 swt4[CIN*3];
    const int co = blockIdx.x;
    const int b  = blockIdx.y;
    const int tid = threadIdx.x;
    {
        float* swts = reinterpret_cast<float*>(swt4);
        for (int i = tid; i < CIN*9; i += 192)
            swts[(i/3)*4 + (i%3)] = w[co*CIN*9 + i];
    }
    __syncthreads();

    const int dg = tid & 7;        // d-chunk 0..7
    const int j  = tid >> 3;       // 0..23
    const int d0 = dg << 2;

    float acc[4] = {0.f, 0.f, 0.f, 0.f};
    const float* xb = in + (size_t)b * in_ct * PX2D;

    for (int ci = 0; ci < CIN; ci++) {
        const float* xc = xb + ci * PX2D;
        #pragma unroll
        for (int kj = 0; kj < 3; kj++) {
            const int jj = j + kj - 1;
            float r[6];
            if (jj >= 0 && jj < JJ) {
                const float* rp = xc + jj*32 + d0;
                float4 m = *reinterpret_cast<const float4*>(rp);
                r[1] = m.x; r[2] = m.y; r[3] = m.z; r[4] = m.w;
                r[0] = (d0 > 0)  ? rp[-1] : 0.f;
                r[5] = (d0 < 28) ? rp[4]  : 0.f;
            } else {
                #pragma unroll
                for (int t = 0; t < 6; t++) r[t] = 0.f;
            }
            const float4 wv = swt4[ci*3 + kj];
            #pragma unroll
            for (int di = 0; di < 4; di++)
                acc[di] = fmaf(wv.x, r[di], fmaf(wv.y, r[di+1], fmaf(wv.z, r[di+2], acc[di])));
        }
    }

    const float a  = PRELU ? alpha[0] : 0.f;
    const float bv = bias[co];
    float* op = out + (size_t)(b*out_ct + co)*PX2D + j*32 + d0;
    #pragma unroll
    for (int di = 0; di < 4; di++) {
        float rr = acc[di] + bv;
        if (PRELU) rr = rr >= 0.f ? rr : a * rr;
        if (RES) op[di] += rr; else op[di] = rr;
    }
}

// ---------------------------------------------------------------------------
// adjoint: back[b,v] = sum_{j,d} A[b,j,v,d] * dual0[b,j,d]   (fp16 matrix)
// 2 v per warp, half2 loads -> full 128B wavefronts, half the loop trips.
// lane = hv(1) x dp(4bits): v = v0 + wrp*2 + hv, d-pair dp (d = 2dp, 2dp+1)
// ---------------------------------------------------------------------------
__global__ void adjoint_kernel() {
    __shared__ float sd[PX2D];
    const int b  = blockIdx.x / (NV/16);
    const int v0 = (blockIdx.x % (NV/16)) * 16;
    for (int i = threadIdx.x; i < PX2D; i += 256)
        sd[i] = g_x2d[(size_t)(b*7 + 0)*PX2D + i];
    __syncthreads();
    const int wrp = threadIdx.x >> 5, lane = threadIdx.x & 31;
    const int hv = lane >> 4;
    const int dp = lane & 15;
    const int v  = v0 + wrp*2 + hv;
    const __half2* Ab = reinterpret_cast<const __half2*>(g_A_h) + (size_t)b * JJ * NV * 16;
    float acc = 0.f;
    #pragma unroll
    for (int j = 0; j < JJ; j++) {
        __half2 av = __ldcs(Ab + ((size_t)j*NV + v)*16 + dp);
        float2 p = __half22float2(av);
        const float2 s = *reinterpret_cast<const float2*>(&sd[j*32 + 2*dp]);
        acc = fmaf(p.x, s.x, fmaf(p.y, s.y, acc));
    }
    #pragma unroll
    for (int off = 8; off; off >>= 1) acc += __shfl_down_sync(0xffffffffu, acc, off);
    if (dp == 0) {
        int z = v & 31, y = (v >> 5) & 31, x = v >> 10;
        g_y3d[(size_t)(b*6 + 5)*NV + (z*32 + y)*32 + x] = acc;
    }
}

// ---------------------------------------------------------------------------
// 3D conv 3x3x3 SAME over 32^3, direct-from-global register blocking.
// Exact R3 structure (fastest measured): block = (co-group, z-plane, b),
// 128 threads (4 xg x 32 y). Thread = 8 consecutive x outputs x COPB co.
// ---------------------------------------------------------------------------
template<int CIN, int COPB, bool PRELU, bool RES>
__global__ void __launch_bounds__(128)
conv3d_kernel(const float* __restrict__ in, int in_ct,
              const float* __restrict__ w,
              const float* __restrict__ bias,
              const float* __restrict__ alpha,
              float* __restrict__ out, int out_ct) {
    __shared__ float swt[COPB*CIN*27];
    const int b   = blockIdx.z;
    const int z   = blockIdx.y;
    const int cg  = blockIdx.x;
    const int tid = threadIdx.x;

    for (int i = tid; i < COPB*CIN*27; i += 128)
        swt[i] = w[(size_t)cg*COPB*CIN*27 + i];
    __syncthreads();

    const int xg = tid & 3;
    const int y  = tid >> 2;
    const int x0 = xg << 3;

    float acc[COPB][8];
    #pragma unroll
    for (int c = 0; c < COPB; c++)
        #pragma unroll
        for (int xi = 0; xi < 8; xi++) acc[c][xi] = 0.f;

    for (int ci = 0; ci < CIN; ci++) {
        const float* pc = in + ((size_t)(b*in_ct + ci) << 15);
        #pragma unroll
        for (int kz = 0; kz < 3; kz++) {
            const int zz = z + kz - 1;
            if (zz < 0 || zz >= 32) continue;      // uniform per block
            #pragma unroll
            for (int ky = 0; ky < 3; ky++) {
                const int yy = y + ky - 1;
                float r[10];
                if (yy >= 0 && yy < 32) {
                    const float* rp = pc + ((zz << 5) + yy)*32 + x0;
                    float4 m0 = *reinterpret_cast<const float4*>(rp);
                    float4 m1 = *reinterpret_cast<const float4*>(rp + 4);
                    r[1] = m0.x; r[2] = m0.y; r[3] = m0.z; r[4] = m0.w;
                    r[5] = m1.x; r[6] = m1.y; r[7] = m1.z; r[8] = m1.w;
                    r[0] = (x0 > 0)  ? rp[-1] : 0.f;
                    r[9] = (x0 < 24) ? rp[8]  : 0.f;
                } else {
                    #pragma unroll
                    for (int t = 0; t < 10; t++) r[t] = 0.f;
                }
                #pragma unroll
                for (int co = 0; co < COPB; co++) {
                    const float* wp = &swt[(co*CIN + ci)*27 + kz*9 + ky*3];
                    const float w0 = wp[0], w1 = wp[1], w2 = wp[2];
                    #pragma unroll
                    for (int xi = 0; xi < 8; xi++)
                        acc[co][xi] = fmaf(w0, r[xi],
                                      fmaf(w1, r[xi+1],
                                      fmaf(w2, r[xi+2], acc[co][xi])));
                }
            }
        }
    }

    const float a = PRELU ? alpha[0] : 0.f;
    #pragma unroll
    for (int co = 0; co < COPB; co++) {
        const float bv = bias[cg*COPB + co];
        float* op = out + ((size_t)(b*out_ct + cg*COPB + co) << 15) + (z << 10) + (y << 5) + x0;
        #pragma unroll
        for (int xi = 0; xi < 8; xi++) {
            float rr = acc[co][xi] + bv;
            if (PRELU) rr = rr >= 0.f ? rr : a * rr;
            if (RES) op[xi] += rr; else op[xi] = rr;
        }
    }
}

// ---------------------------------------------------------------------------
// Output: primal channel 0
// ---------------------------------------------------------------------------
__global__ void out_kernel(float* __restrict__ out) {
    int i = blockIdx.x * blockDim.x + threadIdx.x;
    if (i >= BB*NV) return;
    int b = i / NV, v = i % NV;
    out[i] = g_y3d[(size_t)b*6*NV + v];
}

// ---------------------------------------------------------------------------
extern "C" void kernel_launch(void* const* d_in, const int* in_sizes, int n_in,
                              void* d_out, int out_size) {
    (void)in_sizes; (void)n_in; (void)out_size;
    const float* dual   = (const float*)d_in[0];
    const float* primal = (const float*)d_in[1];
    const float* g      = (const float*)d_in[2];
    const float* An     = (const float*)d_in[3];
    const float* A      = (const float*)d_in[4];
    const float* dw1 = (const float*)d_in[5];  const float* db1 = (const float*)d_in[6];
    const float* da1 = (const float*)d_in[7];
    const float* dw2 = (const float*)d_in[8];  const float* db2 = (const float*)d_in[9];
    const float* da2 = (const float*)d_in[10];
    const float* dw3 = (const float*)d_in[11]; const float* db3 = (const float*)d_in[12];
    const float* pw1 = (const float*)d_in[13]; const float* pb1 = (const float*)d_in[14];
    const float* pa1 = (const float*)d_in[15];
    const float* pw2 = (const float*)d_in[16]; const float* pb2 = (const float*)d_in[17];
    const float* pa2 = (const float*)d_in[18];
    const float* pw3 = (const float*)d_in[19]; const float* pb3 = (const float*)d_in[20];

    float *px2d, *ph2a, *ph2b, *py3d, *ph3a, *ph3b;
    cudaGetSymbolAddress((void**)&px2d, g_x2d);
    cudaGetSymbolAddress((void**)&ph2a, g_h2a);
    cudaGetSymbolAddress((void**)&ph2b, g_h2b);
    cudaGetSymbolAddress((void**)&py3d, g_y3d);
    cudaGetSymbolAddress((void**)&ph3a, g_h3a);
    cudaGetSymbolAddress((void**)&ph3b, g_h3b);
    __half2 *pAn_h, *pA_h;
    cudaGetSymbolAddress((void**)&pAn_h, g_An_h);
    cudaGetSymbolAddress((void**)&pA_h,  g_A_h);

    // one-time per launch: fp16 copies of both projection matrices
    const int n4 = NMAT / 4;
    cvt_half_kernel<<<dim3(n4/256, 2), 256>>>(An, A, pAn_h, pA_h, n4);

    init_kernel<<<(BB*5*NV + 255)/256, 256>>>(dual, g, primal);

    for (int k = 0; k < 10; k++) {
        // --- dual space ---
        gather_f_kernel<<<(BB*NV + 255)/256, 256>>>();
        evalop1_kernel<<<BB*PX2D/4, 256>>>();

        conv2d_kernel<7, true, false><<<dim3(32, BB), 192>>>(
            px2d, 7, dw1 + (size_t)k*32*7*9, db1 + k*32, da1 + k, ph2a, 32);
        conv2d_kernel<32, true, false><<<dim3(32, BB), 192>>>(
            ph2a, 32, dw2 + (size_t)k*32*32*9, db2 + k*32, da2 + k, ph2b, 32);
        conv2d_kernel<32, false, true><<<dim3(5, BB), 192>>>(
            ph2b, 32, dw3 + (size_t)k*5*32*9, db3 + k*5, nullptr, px2d, 7);

        // --- adjoint ---
        adjoint_kernel<<<BB*NV/16, 256>>>();

        // --- primal space (exact R3 scalar conv3d) ---
        conv3d_kernel<6, 4, true, false><<<dim3(8, 32, BB), 128>>>(
            py3d, 6, pw1 + (size_t)k*32*6*27, pb1 + k*32, pa1 + k, ph3a, 32);
        conv3d_kernel<32, 4, true, false><<<dim3(8, 32, BB), 128>>>(
            ph3a, 32, pw2 + (size_t)k*32*32*27, pb2 + k*32, pa2 + k, ph3b, 32);
        conv3d_kernel<32, 1, false, true><<<dim3(5, 32, BB), 128>>>(
            ph3b, 32, pw3 + (size_t)k*5*32*27, pb3 + k*5, nullptr, py3d, 6);
    }

    out_kernel<<<(BB*NV + 255)/256, 256>>>((float*)d_out);
}